// round 14
// baseline (speedup 1.0000x reference)
#include <cuda_runtime.h>
#include <cuda_bf16.h>

#define FULLMASK 0xffffffffu
typedef unsigned long long u64;

// Packed f32x2 helpers (sm_103a). add/mul/fma.rn.f32x2 round each 32-bit half
// exactly like the scalar .rn ops -> bit-identical to the reference dataflow.
// fma(a, -1, b) computes b-a exactly then rounds once == rn(b-a).
__device__ __forceinline__ u64 pk(float lo, float hi) {
    u64 r; asm("mov.b64 %0,{%1,%2};" : "=l"(r) : "f"(lo), "f"(hi)); return r;
}
__device__ __forceinline__ void upk(u64 v, float& lo, float& hi) {
    asm("mov.b64 {%0,%1},%2;" : "=f"(lo), "=f"(hi) : "l"(v));
}
__device__ __forceinline__ u64 f2add(u64 a, u64 b) {
    u64 r; asm("add.rn.f32x2 %0,%1,%2;" : "=l"(r) : "l"(a), "l"(b)); return r;
}
__device__ __forceinline__ u64 f2mul(u64 a, u64 b) {
    u64 r; asm("mul.rn.f32x2 %0,%1,%2;" : "=l"(r) : "l"(a), "l"(b)); return r;
}
__device__ __forceinline__ u64 f2fma(u64 a, u64 b, u64 c) {
    u64 r; asm("fma.rn.f32x2 %0,%1,%2,%3;" : "=l"(r) : "l"(a), "l"(b), "l"(c)); return r;
}

// One warp per 32x32 patch, lane = column. Two rows per iteration, f32x2-packed
// front and tail (R11: scalar tail is slower; ptxas CSEs pack-boundary MOVs).
// 8x-scaled gradient domain (exact power-of-2; EPS pre-scaled).
// LESSON (R8): every float feeding the histogram weights follows the
// reference's exact rounding chain (rn mul/add, sqrt.rn, libdevice atan2f).
// Division by 2*pi via packed Markstein fma (correctly rounded == div.rn).
// floor double-clamped to [36,71]: ob==72 re-routes exactly (w1f 0->1); the
// ulp-rare ob<36 case re-routes ~6e-8*mag (incoherent, ~100x below flip
// threshold). 37-row per-lane histogram, row = floor-36, row r == bin r,
// row 36 aliases bin 0. 9472 B/block -> 24 blocks/SM (48 warps theoretical).
// hist[row][lane]: bank == lane, conflict-free, no atomics.
// R14: PERSISTENT warps — exactly one wave (148*24 blocks); each warp
// grid-strides over ~9 patches. Kills the 9.2-wave tail + transitions.
// Per-patch body is arithmetically identical to R13.

__global__ void __launch_bounds__(64, 24)
pdgo_kernel(const float* __restrict__ patches, float* __restrict__ out, int B)
{
    __shared__ float hist[2][37 * 32];   // 9472 B/block

    const int warp = threadIdx.x >> 5;
    const int lane = threadIdx.x & 31;
    const int gwarp  = blockIdx.x * 2 + warp;
    const int stride = gridDim.x * 2;

    float* hw = hist[warp];
    float* hl = hw + lane;

    constexpr float C2PI   = 6.28318530717958647692f;   // f32 2*pi (0x40C90FDB)
    constexpr float RCP2PI = 1.0f / C2PI;               // rn reciprocal, folded

    const u64 TWO2   = pk(2.0f, 2.0f);
    const u64 EPS8   = pk(8e-8f, 8e-8f);     // 8 * f32(1e-8), exact scaling
    const u64 EPS64  = pk(6.4e-7f, 6.4e-7f); // 64 * f32(1e-8), exact scaling
    const u64 TWOPI2 = pk(C2PI, C2PI);
    const u64 PI2    = pk(3.14159265358979323846f, 3.14159265358979323846f);
    const u64 C36_2  = pk(36.0f, 36.0f);
    const u64 RCP2   = pk(RCP2PI, RCP2PI);
    const u64 NC2PI2 = pk(-C2PI, -C2PI);
    const u64 ONE2   = pk(1.0f, 1.0f);
    const u64 NONE2  = pk(-1.0f, -1.0f);

    for (int pIdx = gwarp; pIdx < B; pIdx += stride) {

        // Flattened init: 1184 floats = 296 float4
        {
            float4 z = make_float4(0.0f, 0.0f, 0.0f, 0.0f);
            float4* h4 = (float4*)hw;
            #pragma unroll
            for (int i = 0; i < 9; ++i) h4[i * 32 + lane] = z;
            if (lane < 8) h4[9 * 32 + lane] = z;
        }
        __syncwarp();

        const float* p = patches + (size_t)pIdx * 1024 + lane;

        // rows (r, r+1): lo half = row r, hi half = row r+1; window rm1..r2
        auto pair_body = [&](float rm1, float r0v, float r1v, float r2v) {
            u64 cv = pk(r0v, r1v);
            u64 pv = pk(rm1, r0v);
            u64 nv = pk(r1v, r2v);
            // t = (2*c + p) + n ; rn(2c+p) == rn((c+c)+p) since 2c is exact
            u64 t2x = f2add(f2fma(TWO2, cv, pv), nv);
            u64 dd2 = f2fma(pv, NONE2, nv);               // rn(n - p), exact fold

            u64 tl = __shfl_up_sync(FULLMASK, t2x, 1);    // lane0 keeps own -> edge pad
            u64 tr = __shfl_down_sync(FULLMASK, t2x, 1);  // lane31 keeps own -> edge pad
            u64 dl = __shfl_up_sync(FULLMASK, dd2, 1);
            u64 dr = __shfl_down_sync(FULLMASK, dd2, 1);

            u64 ux2 = f2fma(tl, NONE2, tr);               // rn(tr - tl) = 8*gx
            u64 uy2 = f2add(f2fma(TWO2, dd2, dl), dr);    // 8*gy

            u64 xs2 = f2add(ux2, EPS8);                   // 8*(gx+eps), exact .rn
            // m2: reference rounding order -- rn(rn(ux^2) + rn(uy^2)) + eps
            u64 m22 = f2add(f2add(f2mul(ux2, ux2), f2mul(uy2, uy2)), EPS64);

            float m2l, m2h; upk(m22, m2l, m2h);
            float magl = __fsqrt_rn(m2l), magh = __fsqrt_rn(m2h);   // 8*mag, exact
            float uyl, uyh, xsl, xsh;
            upk(uy2, uyl, uyh); upk(xs2, xsl, xsh);
            float oril = atan2f(uyl, xsl);   // == atan2f(gy, xs): scale-invariant
            float orih = atan2f(uyh, xsh);

            u64 ch = f2mul(C36_2, f2add(f2add(pk(oril, orih), TWOPI2), PI2)); // t3

            // ob = rn(t3 / 2pi) via packed Markstein sequence (correctly rounded)
            u64 q0  = f2mul(ch, RCP2);
            u64 rr  = f2fma(NC2PI2, q0, ch);              // exact residual
            u64 ob2 = f2fma(rr, RCP2, q0);

            float obl, obh; upk(ob2, obl, obh);
            // double clamp floor to [36, 71] (see header comment)
            float fbl = fminf(fmaxf(floorf(obl), 36.0f), 71.0f);
            float fbh = fminf(fmaxf(floorf(obh), 36.0f), 71.0f);
            u64 w1f2 = f2fma(pk(fbl, fbh), NONE2, ob2);   // rn(ob - fb), exact fold
            u64 mag2 = pk(magl, magh);
            u64 onem = f2fma(w1f2, NONE2, ONE2);          // rn(1 - w1f)
            u64 w0v2 = f2mul(onem, mag2);
            u64 w1v2 = f2mul(w1f2, mag2);

            float w0l, w0h, w1vl, w1vh;
            upk(w0v2, w0l, w0h); upk(w1v2, w1vl, w1vh);

            // row = floor - 36 in [0, 35]; row+1 in [1, 36]; row 36 = bin-0 alias
            int rl = (int)fbl * 32 - 36 * 32;
            hl[rl]      += w0l;
            hl[rl + 32] += w1vl;
            int rh = (int)fbh * 32 - 36 * 32;
            hl[rh]      += w0h;
            hl[rh + 32] += w1vh;
        };

        float r0v = __ldcs(p);        // row 0
        float rm1 = r0v;              // edge pad: row -1 == row 0

        #pragma unroll 5
        for (int k = 0; k < 15; ++k) {
            float r1v = __ldcs(p + (2 * k + 1) * 32);
            float r2v = __ldcs(p + (2 * k + 2) * 32);
            pair_body(rm1, r0v, r1v, r2v);
            rm1 = r1v; r0v = r2v;
        }
        {   // rows 30,31: row 32 clamps to row 31
            float r1v = __ldcs(p + 31 * 32);
            pair_body(rm1, r0v, r1v, r1v);
        }
        __syncwarp();

        // Reduce 32 lane-private copies per row; rotated reads (conflict-free),
        // 2 independent accumulators halve the serial FADD chain.
        const int rowA = lane;                                  // rows 0..31
        const int rowB = 32 + lane;                             // rows 32..36 (lanes 0..4)
        float sA0 = 0.0f, sA1 = 0.0f, sB0 = 0.0f, sB1 = 0.0f;
        #pragma unroll
        for (int k = 0; k < 32; k += 2) {
            int l0 = (lane + k) & 31;
            int l1 = (lane + k + 1) & 31;
            sA0 = __fadd_rn(sA0, hw[rowA * 32 + l0]);
            sA1 = __fadd_rn(sA1, hw[rowA * 32 + l1]);
            if (lane < 5) {
                sB0 = __fadd_rn(sB0, hw[rowB * 32 + l0]);
                sB1 = __fadd_rn(sB1, hw[rowB * 32 + l1]);
            }
        }
        float s0 = __fadd_rn(sA0, sA1);
        float s1 = __fadd_rn(sB0, sB1);
        __syncwarp();
        // Diagonal slots: slot i at hw[i*32 + (i & 31)]  (bank = i mod 32)
        hw[rowA * 32 + (rowA & 31)] = s0;                       // slots 0..31
        if (lane < 5) hw[rowB * 32 + (rowB & 31)] = s1;         // slots 32..36
        __syncwarp();
        // Fold alias: bin 0 += row 36 (appended-last add order; tolerated class)
        if (lane == 0) hw[0] = __fadd_rn(hw[0], hw[36 * 32 + 4]);
        __syncwarp();

        auto hbin = [&](int b) { return hw[b * 32 + (b & 31)]; };

        // sm[b] = (0.33*h[b-1] + 0.34*h[b]) + 0.33*h[b+1]  (no fma contraction)
        int bm = (lane == 0) ? 35 : lane - 1;
        int bp = lane + 1;   // lane 31 -> bin 32, valid
        float sm0 = __fadd_rn(__fadd_rn(__fmul_rn(0.33f, hbin(bm)),
                                        __fmul_rn(0.34f, hbin(lane))),
                              __fmul_rn(0.33f, hbin(bp)));
        float bv = sm0; int bi = lane;
        if (lane < 4) {
            int bb  = 32 + lane;
            int bm2 = bb - 1;
            int bp2 = (bb == 35) ? 0 : bb + 1;
            float sm1 = __fadd_rn(__fadd_rn(__fmul_rn(0.33f, hbin(bm2)),
                                            __fmul_rn(0.34f, hbin(bb))),
                                  __fmul_rn(0.33f, hbin(bp2)));
            if (sm1 > bv) { bv = sm1; bi = bb; }  // strict >: tie keeps lower index
        }
        #pragma unroll
        for (int o = 16; o > 0; o >>= 1) {
            float ov = __shfl_xor_sync(FULLMASK, bv, o);
            int   oi = __shfl_xor_sync(FULLMASK, bi, o);
            if (ov > bv || (ov == bv && oi < bi)) { bv = ov; bi = oi; }
        }
        if (lane == 0) {
            float fi = (float)bi;
            float v  = __fmul_rn(6.28318530717958647692f, fi);
            v = __fdiv_rn(v, 36.0f);
            out[pIdx] = -(__fadd_rn(v, -3.14159265358979323846f));
        }
        __syncwarp();
    }
}

extern "C" void kernel_launch(void* const* d_in, const int* in_sizes, int n_in,
                              void* d_out, int out_size)
{
    cudaFuncSetAttribute(pdgo_kernel,
                         cudaFuncAttributePreferredSharedMemoryCarveout, 100);
    const float* patch = (const float*)d_in[0];
    float* out = (float*)d_out;
    int B = in_sizes[0] / 1024;      // 32*32 per patch
    int blocks = 148 * 24;           // exactly one resident wave (persistent)
    pdgo_kernel<<<blocks, 64>>>(patch, out, B);
}

// round 15
// speedup vs baseline: 1.3873x; 1.3873x over previous
#include <cuda_runtime.h>
#include <cuda_bf16.h>

#define FULLMASK 0xffffffffu
typedef unsigned long long u64;

// Packed f32x2 helpers (sm_103a). add/mul/fma.rn.f32x2 round each 32-bit half
// exactly like the scalar .rn ops -> bit-identical to the reference dataflow.
// fma(a, -1, b) computes b-a exactly then rounds once == rn(b-a).
__device__ __forceinline__ u64 pk(float lo, float hi) {
    u64 r; asm("mov.b64 %0,{%1,%2};" : "=l"(r) : "f"(lo), "f"(hi)); return r;
}
__device__ __forceinline__ void upk(u64 v, float& lo, float& hi) {
    asm("mov.b64 {%0,%1},%2;" : "=f"(lo), "=f"(hi) : "l"(v));
}
__device__ __forceinline__ u64 f2add(u64 a, u64 b) {
    u64 r; asm("add.rn.f32x2 %0,%1,%2;" : "=l"(r) : "l"(a), "l"(b)); return r;
}
__device__ __forceinline__ u64 f2mul(u64 a, u64 b) {
    u64 r; asm("mul.rn.f32x2 %0,%1,%2;" : "=l"(r) : "l"(a), "l"(b)); return r;
}
__device__ __forceinline__ u64 f2fma(u64 a, u64 b, u64 c) {
    u64 r; asm("fma.rn.f32x2 %0,%1,%2,%3;" : "=l"(r) : "l"(a), "l"(b), "l"(c)); return r;
}

// One warp per 32x32 patch, lane = column. Two rows per iteration, f32x2-packed
// front and tail (R11: scalar tail is slower; ptxas CSEs pack-boundary MOVs).
// 8x-scaled gradient domain (exact power-of-2; EPS pre-scaled).
// LESSON (R8): every float feeding the histogram weights follows the
// reference's exact rounding chain (rn mul/add, sqrt.rn, libdevice atan2f).
// LESSON (R14): no persistent warps — block-level refill software-pipelines
// across patches; warp-level persistence exposes GMEM latency at every
// patch boundary in lockstep (-50%).
// Division by 2*pi via packed Markstein fma (correctly rounded == div.rn).
// floor double-clamped to [36,71]: ob==72 re-routes exactly (w1f 0->1); the
// ulp-rare ob<36 case re-routes ~6e-8*mag (incoherent, ~100x below flip
// threshold). 37-row per-lane histogram, row = floor-36, row r == bin r,
// row 36 aliases bin 0. 9472 B/block -> 24 blocks/SM (48 warps theoretical).
// hist[row][lane]: bank == lane, conflict-free, no atomics.
// R15: full unroll of the 15-pair mainloop (flat scheduling window; body
// ~23KB SASS fits L1.5 I$).

__global__ void __launch_bounds__(64, 24)
pdgo_kernel(const float* __restrict__ patches, float* __restrict__ out, int B)
{
    __shared__ float hist[2][37 * 32];   // 9472 B/block

    const int warp = threadIdx.x >> 5;
    const int lane = threadIdx.x & 31;
    const int pIdx = blockIdx.x * 2 + warp;
    if (pIdx >= B) return;

    float* hw = hist[warp];
    float* hl = hw + lane;

    // Flattened init: 1184 floats = 296 float4
    {
        float4 z = make_float4(0.0f, 0.0f, 0.0f, 0.0f);
        float4* h4 = (float4*)hw;
        #pragma unroll
        for (int i = 0; i < 9; ++i) h4[i * 32 + lane] = z;
        if (lane < 8) h4[9 * 32 + lane] = z;
    }
    __syncwarp();

    const float* p = patches + (size_t)pIdx * 1024 + lane;

    constexpr float C2PI   = 6.28318530717958647692f;   // f32 2*pi (0x40C90FDB)
    constexpr float RCP2PI = 1.0f / C2PI;               // rn reciprocal, folded

    const u64 TWO2   = pk(2.0f, 2.0f);
    const u64 EPS8   = pk(8e-8f, 8e-8f);     // 8 * f32(1e-8), exact scaling
    const u64 EPS64  = pk(6.4e-7f, 6.4e-7f); // 64 * f32(1e-8), exact scaling
    const u64 TWOPI2 = pk(C2PI, C2PI);
    const u64 PI2    = pk(3.14159265358979323846f, 3.14159265358979323846f);
    const u64 C36_2  = pk(36.0f, 36.0f);
    const u64 RCP2   = pk(RCP2PI, RCP2PI);
    const u64 NC2PI2 = pk(-C2PI, -C2PI);
    const u64 ONE2   = pk(1.0f, 1.0f);
    const u64 NONE2  = pk(-1.0f, -1.0f);

    // rows (r, r+1): lo half = row r, hi half = row r+1; window rm1..r2
    auto pair_body = [&](float rm1, float r0v, float r1v, float r2v) {
        u64 cv = pk(r0v, r1v);
        u64 pv = pk(rm1, r0v);
        u64 nv = pk(r1v, r2v);
        // t = (2*c + p) + n ; rn(2c+p) == rn((c+c)+p) since 2c is exact
        u64 t2x = f2add(f2fma(TWO2, cv, pv), nv);
        u64 dd2 = f2fma(pv, NONE2, nv);               // rn(n - p), exact fold

        u64 tl = __shfl_up_sync(FULLMASK, t2x, 1);    // lane0 keeps own -> edge pad
        u64 tr = __shfl_down_sync(FULLMASK, t2x, 1);  // lane31 keeps own -> edge pad
        u64 dl = __shfl_up_sync(FULLMASK, dd2, 1);
        u64 dr = __shfl_down_sync(FULLMASK, dd2, 1);

        u64 ux2 = f2fma(tl, NONE2, tr);               // rn(tr - tl) = 8*gx
        u64 uy2 = f2add(f2fma(TWO2, dd2, dl), dr);    // 8*gy

        u64 xs2 = f2add(ux2, EPS8);                   // 8*(gx+eps), exact .rn
        // m2: reference rounding order -- rn(rn(ux^2) + rn(uy^2)) + eps
        u64 m22 = f2add(f2add(f2mul(ux2, ux2), f2mul(uy2, uy2)), EPS64);

        float m2l, m2h; upk(m22, m2l, m2h);
        float magl = __fsqrt_rn(m2l), magh = __fsqrt_rn(m2h);   // 8*mag, exact
        float uyl, uyh, xsl, xsh;
        upk(uy2, uyl, uyh); upk(xs2, xsl, xsh);
        float oril = atan2f(uyl, xsl);   // == atan2f(gy, xs): scale-invariant
        float orih = atan2f(uyh, xsh);

        u64 ch = f2mul(C36_2, f2add(f2add(pk(oril, orih), TWOPI2), PI2)); // t3

        // ob = rn(t3 / 2pi) via packed Markstein sequence (correctly rounded)
        u64 q0  = f2mul(ch, RCP2);
        u64 rr  = f2fma(NC2PI2, q0, ch);              // exact residual
        u64 ob2 = f2fma(rr, RCP2, q0);

        float obl, obh; upk(ob2, obl, obh);
        // double clamp floor to [36, 71] (see header comment)
        float fbl = fminf(fmaxf(floorf(obl), 36.0f), 71.0f);
        float fbh = fminf(fmaxf(floorf(obh), 36.0f), 71.0f);
        u64 w1f2 = f2fma(pk(fbl, fbh), NONE2, ob2);   // rn(ob - fb), exact fold
        u64 mag2 = pk(magl, magh);
        u64 onem = f2fma(w1f2, NONE2, ONE2);          // rn(1 - w1f)
        u64 w0v2 = f2mul(onem, mag2);
        u64 w1v2 = f2mul(w1f2, mag2);

        float w0l, w0h, w1vl, w1vh;
        upk(w0v2, w0l, w0h); upk(w1v2, w1vl, w1vh);

        // row = floor - 36 in [0, 35]; row+1 in [1, 36]; row 36 = bin-0 alias
        int rl = (int)fbl * 32 - 36 * 32;
        hl[rl]      += w0l;
        hl[rl + 32] += w1vl;
        int rh = (int)fbh * 32 - 36 * 32;
        hl[rh]      += w0h;
        hl[rh + 32] += w1vh;
    };

    float r0v = __ldcs(p);        // row 0
    float rm1 = r0v;              // edge pad: row -1 == row 0

    #pragma unroll
    for (int k = 0; k < 15; ++k) {
        float r1v = __ldcs(p + (2 * k + 1) * 32);
        float r2v = __ldcs(p + (2 * k + 2) * 32);
        pair_body(rm1, r0v, r1v, r2v);
        rm1 = r1v; r0v = r2v;
    }
    {   // rows 30,31: row 32 clamps to row 31
        float r1v = __ldcs(p + 31 * 32);
        pair_body(rm1, r0v, r1v, r1v);
    }
    __syncwarp();

    // Reduce 32 lane-private copies per row; rotated reads (conflict-free),
    // 2 independent accumulators halve the serial FADD chain (ordering-noise
    // class, tolerated).
    const int rowA = lane;                                  // rows 0..31 (bins 0..31)
    const int rowB = 32 + lane;                             // rows 32..36 (lanes 0..4)
    float sA0 = 0.0f, sA1 = 0.0f, sB0 = 0.0f, sB1 = 0.0f;
    #pragma unroll
    for (int k = 0; k < 32; k += 2) {
        int l0 = (lane + k) & 31;
        int l1 = (lane + k + 1) & 31;
        sA0 = __fadd_rn(sA0, hw[rowA * 32 + l0]);
        sA1 = __fadd_rn(sA1, hw[rowA * 32 + l1]);
        if (lane < 5) {
            sB0 = __fadd_rn(sB0, hw[rowB * 32 + l0]);
            sB1 = __fadd_rn(sB1, hw[rowB * 32 + l1]);
        }
    }
    float s0 = __fadd_rn(sA0, sA1);
    float s1 = __fadd_rn(sB0, sB1);
    __syncwarp();
    // Diagonal slots: slot i at hw[i*32 + (i & 31)]  (bank = i mod 32)
    hw[rowA * 32 + (rowA & 31)] = s0;                       // slots 0..31
    if (lane < 5) hw[rowB * 32 + (rowB & 31)] = s1;         // slots 32..36
    __syncwarp();
    // Fold alias: bin 0 += row 36 (appended-last add order; tolerated class)
    if (lane == 0) hw[0] = __fadd_rn(hw[0], hw[36 * 32 + 4]);
    __syncwarp();

    auto hbin = [&](int b) { return hw[b * 32 + (b & 31)]; };

    // sm[b] = (0.33*h[b-1] + 0.34*h[b]) + 0.33*h[b+1]  (no fma contraction)
    int bm = (lane == 0) ? 35 : lane - 1;
    int bp = lane + 1;   // lane 31 -> bin 32, valid
    float sm0 = __fadd_rn(__fadd_rn(__fmul_rn(0.33f, hbin(bm)),
                                    __fmul_rn(0.34f, hbin(lane))),
                          __fmul_rn(0.33f, hbin(bp)));
    float bv = sm0; int bi = lane;
    if (lane < 4) {
        int bb  = 32 + lane;
        int bm2 = bb - 1;
        int bp2 = (bb == 35) ? 0 : bb + 1;
        float sm1 = __fadd_rn(__fadd_rn(__fmul_rn(0.33f, hbin(bm2)),
                                        __fmul_rn(0.34f, hbin(bb))),
                              __fmul_rn(0.33f, hbin(bp2)));
        if (sm1 > bv) { bv = sm1; bi = bb; }  // strict >: tie keeps lower index
    }
    #pragma unroll
    for (int o = 16; o > 0; o >>= 1) {
        float ov = __shfl_xor_sync(FULLMASK, bv, o);
        int   oi = __shfl_xor_sync(FULLMASK, bi, o);
        if (ov > bv || (ov == bv && oi < bi)) { bv = ov; bi = oi; }
    }
    if (lane == 0) {
        float fi = (float)bi;
        float v  = __fmul_rn(6.28318530717958647692f, fi);
        v = __fdiv_rn(v, 36.0f);
        out[pIdx] = -(__fadd_rn(v, -3.14159265358979323846f));
    }
}

extern "C" void kernel_launch(void* const* d_in, const int* in_sizes, int n_in,
                              void* d_out, int out_size)
{
    cudaFuncSetAttribute(pdgo_kernel,
                         cudaFuncAttributePreferredSharedMemoryCarveout, 100);
    const float* patch = (const float*)d_in[0];
    float* out = (float*)d_out;
    int B = in_sizes[0] / 1024;      // 32*32 per patch
    int blocks = (B + 1) / 2;        // 2 warps (patches) per 64-thread block
    pdgo_kernel<<<blocks, 64>>>(patch, out, B);
}

// round 16
// speedup vs baseline: 1.5850x; 1.1425x over previous
#include <cuda_runtime.h>
#include <cuda_bf16.h>

#define FULLMASK 0xffffffffu
typedef unsigned long long u64;

// Packed f32x2 helpers (sm_103a). add/mul/fma.rn.f32x2 round each 32-bit half
// exactly like the scalar .rn ops -> bit-identical to the reference dataflow.
// fma(a, -1, b) computes b-a exactly then rounds once == rn(b-a).
__device__ __forceinline__ u64 pk(float lo, float hi) {
    u64 r; asm("mov.b64 %0,{%1,%2};" : "=l"(r) : "f"(lo), "f"(hi)); return r;
}
__device__ __forceinline__ void upk(u64 v, float& lo, float& hi) {
    asm("mov.b64 {%0,%1},%2;" : "=f"(lo), "=f"(hi) : "l"(v));
}
__device__ __forceinline__ u64 f2add(u64 a, u64 b) {
    u64 r; asm("add.rn.f32x2 %0,%1,%2;" : "=l"(r) : "l"(a), "l"(b)); return r;
}
__device__ __forceinline__ u64 f2mul(u64 a, u64 b) {
    u64 r; asm("mul.rn.f32x2 %0,%1,%2;" : "=l"(r) : "l"(a), "l"(b)); return r;
}
__device__ __forceinline__ u64 f2fma(u64 a, u64 b, u64 c) {
    u64 r; asm("fma.rn.f32x2 %0,%1,%2,%3;" : "=l"(r) : "l"(a), "l"(b), "l"(c)); return r;
}

// One warp per 32x32 patch, lane = column. Two rows per iteration, f32x2-packed
// front and tail (R11: scalar tail is slower; ptxas CSEs pack-boundary MOVs).
// 8x-scaled gradient domain (exact power-of-2; EPS pre-scaled).
// LESSON (R8): every float feeding the histogram weights follows the
// reference's exact rounding chain (rn mul/add, sqrt.rn, libdevice atan2f).
// LESSON (R14): no persistent warps (block refill > warp persistence, -50%).
// LESSON (R15): full unroll spills L0 I$ (issue 84->76); unroll 5 is the spot.
// Division by 2*pi via packed Markstein fma (correctly rounded == div.rn).
// floor double-clamped to [36,71]: ob==72 re-routes exactly (w1f 0->1); the
// ulp-rare ob<36 case re-routes ~6e-8*mag (incoherent, ~100x below flip
// threshold). 37-row per-lane histogram, row = floor-36, row r == bin r,
// row 36 aliases bin 0. 9472 B/block -> 24 blocks/SM (48 warps theoretical).
// hist[row][lane]: bank == lane, conflict-free, no atomics.
// R16: explicit one-pair-ahead load rotation (software double-buffer) so the
// next pair's LDGs issue before the current pair_body, covering L2/DRAM
// latency across unroll seams. Zero float-op changes vs R13.

__global__ void __launch_bounds__(64, 24)
pdgo_kernel(const float* __restrict__ patches, float* __restrict__ out, int B)
{
    __shared__ float hist[2][37 * 32];   // 9472 B/block

    const int warp = threadIdx.x >> 5;
    const int lane = threadIdx.x & 31;
    const int pIdx = blockIdx.x * 2 + warp;
    if (pIdx >= B) return;

    float* hw = hist[warp];
    float* hl = hw + lane;

    // Flattened init: 1184 floats = 296 float4
    {
        float4 z = make_float4(0.0f, 0.0f, 0.0f, 0.0f);
        float4* h4 = (float4*)hw;
        #pragma unroll
        for (int i = 0; i < 9; ++i) h4[i * 32 + lane] = z;
        if (lane < 8) h4[9 * 32 + lane] = z;
    }
    __syncwarp();

    const float* p = patches + (size_t)pIdx * 1024 + lane;

    constexpr float C2PI   = 6.28318530717958647692f;   // f32 2*pi (0x40C90FDB)
    constexpr float RCP2PI = 1.0f / C2PI;               // rn reciprocal, folded

    const u64 TWO2   = pk(2.0f, 2.0f);
    const u64 EPS8   = pk(8e-8f, 8e-8f);     // 8 * f32(1e-8), exact scaling
    const u64 EPS64  = pk(6.4e-7f, 6.4e-7f); // 64 * f32(1e-8), exact scaling
    const u64 TWOPI2 = pk(C2PI, C2PI);
    const u64 PI2    = pk(3.14159265358979323846f, 3.14159265358979323846f);
    const u64 C36_2  = pk(36.0f, 36.0f);
    const u64 RCP2   = pk(RCP2PI, RCP2PI);
    const u64 NC2PI2 = pk(-C2PI, -C2PI);
    const u64 ONE2   = pk(1.0f, 1.0f);
    const u64 NONE2  = pk(-1.0f, -1.0f);

    // rows (r, r+1): lo half = row r, hi half = row r+1; window rm1..r2
    auto pair_body = [&](float rm1, float r0v, float r1v, float r2v) {
        u64 cv = pk(r0v, r1v);
        u64 pv = pk(rm1, r0v);
        u64 nv = pk(r1v, r2v);
        // t = (2*c + p) + n ; rn(2c+p) == rn((c+c)+p) since 2c is exact
        u64 t2x = f2add(f2fma(TWO2, cv, pv), nv);
        u64 dd2 = f2fma(pv, NONE2, nv);               // rn(n - p), exact fold

        u64 tl = __shfl_up_sync(FULLMASK, t2x, 1);    // lane0 keeps own -> edge pad
        u64 tr = __shfl_down_sync(FULLMASK, t2x, 1);  // lane31 keeps own -> edge pad
        u64 dl = __shfl_up_sync(FULLMASK, dd2, 1);
        u64 dr = __shfl_down_sync(FULLMASK, dd2, 1);

        u64 ux2 = f2fma(tl, NONE2, tr);               // rn(tr - tl) = 8*gx
        u64 uy2 = f2add(f2fma(TWO2, dd2, dl), dr);    // 8*gy

        u64 xs2 = f2add(ux2, EPS8);                   // 8*(gx+eps), exact .rn
        // m2: reference rounding order -- rn(rn(ux^2) + rn(uy^2)) + eps
        u64 m22 = f2add(f2add(f2mul(ux2, ux2), f2mul(uy2, uy2)), EPS64);

        float m2l, m2h; upk(m22, m2l, m2h);
        float magl = __fsqrt_rn(m2l), magh = __fsqrt_rn(m2h);   // 8*mag, exact
        float uyl, uyh, xsl, xsh;
        upk(uy2, uyl, uyh); upk(xs2, xsl, xsh);
        float oril = atan2f(uyl, xsl);   // == atan2f(gy, xs): scale-invariant
        float orih = atan2f(uyh, xsh);

        u64 ch = f2mul(C36_2, f2add(f2add(pk(oril, orih), TWOPI2), PI2)); // t3

        // ob = rn(t3 / 2pi) via packed Markstein sequence (correctly rounded)
        u64 q0  = f2mul(ch, RCP2);
        u64 rr  = f2fma(NC2PI2, q0, ch);              // exact residual
        u64 ob2 = f2fma(rr, RCP2, q0);

        float obl, obh; upk(ob2, obl, obh);
        // double clamp floor to [36, 71] (see header comment)
        float fbl = fminf(fmaxf(floorf(obl), 36.0f), 71.0f);
        float fbh = fminf(fmaxf(floorf(obh), 36.0f), 71.0f);
        u64 w1f2 = f2fma(pk(fbl, fbh), NONE2, ob2);   // rn(ob - fb), exact fold
        u64 mag2 = pk(magl, magh);
        u64 onem = f2fma(w1f2, NONE2, ONE2);          // rn(1 - w1f)
        u64 w0v2 = f2mul(onem, mag2);
        u64 w1v2 = f2mul(w1f2, mag2);

        float w0l, w0h, w1vl, w1vh;
        upk(w0v2, w0l, w0h); upk(w1v2, w1vl, w1vh);

        // row = floor - 36 in [0, 35]; row+1 in [1, 36]; row 36 = bin-0 alias
        int rl = (int)fbl * 32 - 36 * 32;
        hl[rl]      += w0l;
        hl[rl + 32] += w1vl;
        int rh = (int)fbh * 32 - 36 * 32;
        hl[rh]      += w0h;
        hl[rh + 32] += w1vh;
    };

    float r0v = __ldcs(p);            // row 0
    float rm1 = r0v;                  // edge pad: row -1 == row 0
    float n1  = __ldcs(p + 1 * 32);   // row 1 (prefetched)
    float n2  = __ldcs(p + 2 * 32);   // row 2 (prefetched)

    #pragma unroll 5
    for (int k = 0; k < 15; ++k) {
        float r1v = n1, r2v = n2;
        if (k < 14) {                 // prefetch next pair's rows before compute
            n1 = __ldcs(p + (2 * k + 3) * 32);
            n2 = __ldcs(p + (2 * k + 4) * 32);
        } else {
            n1 = __ldcs(p + 31 * 32); // row 31 for the final clamped pair
        }
        pair_body(rm1, r0v, r1v, r2v);
        rm1 = r1v; r0v = r2v;
    }
    pair_body(rm1, r0v, n1, n1);      // rows 30,31: row 32 clamps to row 31
    __syncwarp();

    // Reduce 32 lane-private copies per row; rotated reads (conflict-free),
    // 2 independent accumulators halve the serial FADD chain (ordering-noise
    // class, tolerated).
    const int rowA = lane;                                  // rows 0..31 (bins 0..31)
    const int rowB = 32 + lane;                             // rows 32..36 (lanes 0..4)
    float sA0 = 0.0f, sA1 = 0.0f, sB0 = 0.0f, sB1 = 0.0f;
    #pragma unroll
    for (int k = 0; k < 32; k += 2) {
        int l0 = (lane + k) & 31;
        int l1 = (lane + k + 1) & 31;
        sA0 = __fadd_rn(sA0, hw[rowA * 32 + l0]);
        sA1 = __fadd_rn(sA1, hw[rowA * 32 + l1]);
        if (lane < 5) {
            sB0 = __fadd_rn(sB0, hw[rowB * 32 + l0]);
            sB1 = __fadd_rn(sB1, hw[rowB * 32 + l1]);
        }
    }
    float s0 = __fadd_rn(sA0, sA1);
    float s1 = __fadd_rn(sB0, sB1);
    __syncwarp();
    // Diagonal slots: slot i at hw[i*32 + (i & 31)]  (bank = i mod 32)
    hw[rowA * 32 + (rowA & 31)] = s0;                       // slots 0..31
    if (lane < 5) hw[rowB * 32 + (rowB & 31)] = s1;         // slots 32..36
    __syncwarp();
    // Fold alias: bin 0 += row 36 (appended-last add order; tolerated class)
    if (lane == 0) hw[0] = __fadd_rn(hw[0], hw[36 * 32 + 4]);
    __syncwarp();

    auto hbin = [&](int b) { return hw[b * 32 + (b & 31)]; };

    // sm[b] = (0.33*h[b-1] + 0.34*h[b]) + 0.33*h[b+1]  (no fma contraction)
    int bm = (lane == 0) ? 35 : lane - 1;
    int bp = lane + 1;   // lane 31 -> bin 32, valid
    float sm0 = __fadd_rn(__fadd_rn(__fmul_rn(0.33f, hbin(bm)),
                                    __fmul_rn(0.34f, hbin(lane))),
                          __fmul_rn(0.33f, hbin(bp)));
    float bv = sm0; int bi = lane;
    if (lane < 4) {
        int bb  = 32 + lane;
        int bm2 = bb - 1;
        int bp2 = (bb == 35) ? 0 : bb + 1;
        float sm1 = __fadd_rn(__fadd_rn(__fmul_rn(0.33f, hbin(bm2)),
                                        __fmul_rn(0.34f, hbin(bb))),
                              __fmul_rn(0.33f, hbin(bp2)));
        if (sm1 > bv) { bv = sm1; bi = bb; }  // strict >: tie keeps lower index
    }
    #pragma unroll
    for (int o = 16; o > 0; o >>= 1) {
        float ov = __shfl_xor_sync(FULLMASK, bv, o);
        int   oi = __shfl_xor_sync(FULLMASK, bi, o);
        if (ov > bv || (ov == bv && oi < bi)) { bv = ov; bi = oi; }
    }
    if (lane == 0) {
        float fi = (float)bi;
        float v  = __fmul_rn(6.28318530717958647692f, fi);
        v = __fdiv_rn(v, 36.0f);
        out[pIdx] = -(__fadd_rn(v, -3.14159265358979323846f));
    }
}

extern "C" void kernel_launch(void* const* d_in, const int* in_sizes, int n_in,
                              void* d_out, int out_size)
{
    cudaFuncSetAttribute(pdgo_kernel,
                         cudaFuncAttributePreferredSharedMemoryCarveout, 100);
    const float* patch = (const float*)d_in[0];
    float* out = (float*)d_out;
    int B = in_sizes[0] / 1024;      // 32*32 per patch
    int blocks = (B + 1) / 2;        // 2 warps (patches) per 64-thread block
    pdgo_kernel<<<blocks, 64>>>(patch, out, B);
}

// round 17
// speedup vs baseline: 1.5864x; 1.0009x over previous
#include <cuda_runtime.h>
#include <cuda_bf16.h>

#define FULLMASK 0xffffffffu
typedef unsigned long long u64;

// Packed f32x2 helpers (sm_103a). add/mul/fma.rn.f32x2 round each 32-bit half
// exactly like the scalar .rn ops -> bit-identical to the reference dataflow.
// fma(a, -1, b) computes b-a exactly then rounds once == rn(b-a).
__device__ __forceinline__ u64 pk(float lo, float hi) {
    u64 r; asm("mov.b64 %0,{%1,%2};" : "=l"(r) : "f"(lo), "f"(hi)); return r;
}
__device__ __forceinline__ void upk(u64 v, float& lo, float& hi) {
    asm("mov.b64 {%0,%1},%2;" : "=f"(lo), "=f"(hi) : "l"(v));
}
__device__ __forceinline__ u64 f2add(u64 a, u64 b) {
    u64 r; asm("add.rn.f32x2 %0,%1,%2;" : "=l"(r) : "l"(a), "l"(b)); return r;
}
__device__ __forceinline__ u64 f2mul(u64 a, u64 b) {
    u64 r; asm("mul.rn.f32x2 %0,%1,%2;" : "=l"(r) : "l"(a), "l"(b)); return r;
}
__device__ __forceinline__ u64 f2fma(u64 a, u64 b, u64 c) {
    u64 r; asm("fma.rn.f32x2 %0,%1,%2,%3;" : "=l"(r) : "l"(a), "l"(b), "l"(c)); return r;
}

// One warp per 32x32 patch, lane = column. Two rows per iteration, f32x2-packed
// front and tail (R11: scalar tail is slower; ptxas CSEs pack-boundary MOVs).
// 8x-scaled gradient domain (exact power-of-2; EPS pre-scaled).
// LESSON (R8): every float feeding the histogram weights follows the
// reference's exact rounding chain (rn mul/add, sqrt.rn, libdevice atan2f).
// LESSON (R14): no persistent warps (block refill > warp persistence, -50%).
// LESSON (R15): full unroll spills L0 I$ (issue 84->76); unroll 5 is the spot.
// LESSON (R16): one-pair-ahead prefetch covered seam latency (+4.4%).
// Division by 2*pi via packed Markstein fma (correctly rounded == div.rn).
// floor double-clamped to [36,71]: ob==72 re-routes exactly (w1f 0->1); the
// ulp-rare ob<36 case re-routes ~6e-8*mag (incoherent, ~100x below flip
// threshold). 37-row per-lane histogram, row = floor-36, row r == bin r,
// row 36 aliases bin 0. 9472 B/block -> 24 blocks/SM (48 warps theoretical).
// hist[row][lane]: bank == lane, conflict-free, no atomics.
// R17: depth-2 load rotation (4 rows in flight) — ~190 instr of cover per
// load, hides far-L2-class latency; MLP 2->4; branch-free main loop with
// two peeled boundary iterations. Zero float-op changes vs R16.

__global__ void __launch_bounds__(64, 24)
pdgo_kernel(const float* __restrict__ patches, float* __restrict__ out, int B)
{
    __shared__ float hist[2][37 * 32];   // 9472 B/block

    const int warp = threadIdx.x >> 5;
    const int lane = threadIdx.x & 31;
    const int pIdx = blockIdx.x * 2 + warp;
    if (pIdx >= B) return;

    float* hw = hist[warp];
    float* hl = hw + lane;

    // Flattened init: 1184 floats = 296 float4
    {
        float4 z = make_float4(0.0f, 0.0f, 0.0f, 0.0f);
        float4* h4 = (float4*)hw;
        #pragma unroll
        for (int i = 0; i < 9; ++i) h4[i * 32 + lane] = z;
        if (lane < 8) h4[9 * 32 + lane] = z;
    }
    __syncwarp();

    const float* p = patches + (size_t)pIdx * 1024 + lane;

    constexpr float C2PI   = 6.28318530717958647692f;   // f32 2*pi (0x40C90FDB)
    constexpr float RCP2PI = 1.0f / C2PI;               // rn reciprocal, folded

    const u64 TWO2   = pk(2.0f, 2.0f);
    const u64 EPS8   = pk(8e-8f, 8e-8f);     // 8 * f32(1e-8), exact scaling
    const u64 EPS64  = pk(6.4e-7f, 6.4e-7f); // 64 * f32(1e-8), exact scaling
    const u64 TWOPI2 = pk(C2PI, C2PI);
    const u64 PI2    = pk(3.14159265358979323846f, 3.14159265358979323846f);
    const u64 C36_2  = pk(36.0f, 36.0f);
    const u64 RCP2   = pk(RCP2PI, RCP2PI);
    const u64 NC2PI2 = pk(-C2PI, -C2PI);
    const u64 ONE2   = pk(1.0f, 1.0f);
    const u64 NONE2  = pk(-1.0f, -1.0f);

    // rows (r, r+1): lo half = row r, hi half = row r+1; window rm1..r2
    auto pair_body = [&](float rm1, float r0v, float r1v, float r2v) {
        u64 cv = pk(r0v, r1v);
        u64 pv = pk(rm1, r0v);
        u64 nv = pk(r1v, r2v);
        // t = (2*c + p) + n ; rn(2c+p) == rn((c+c)+p) since 2c is exact
        u64 t2x = f2add(f2fma(TWO2, cv, pv), nv);
        u64 dd2 = f2fma(pv, NONE2, nv);               // rn(n - p), exact fold

        u64 tl = __shfl_up_sync(FULLMASK, t2x, 1);    // lane0 keeps own -> edge pad
        u64 tr = __shfl_down_sync(FULLMASK, t2x, 1);  // lane31 keeps own -> edge pad
        u64 dl = __shfl_up_sync(FULLMASK, dd2, 1);
        u64 dr = __shfl_down_sync(FULLMASK, dd2, 1);

        u64 ux2 = f2fma(tl, NONE2, tr);               // rn(tr - tl) = 8*gx
        u64 uy2 = f2add(f2fma(TWO2, dd2, dl), dr);    // 8*gy

        u64 xs2 = f2add(ux2, EPS8);                   // 8*(gx+eps), exact .rn
        // m2: reference rounding order -- rn(rn(ux^2) + rn(uy^2)) + eps
        u64 m22 = f2add(f2add(f2mul(ux2, ux2), f2mul(uy2, uy2)), EPS64);

        float m2l, m2h; upk(m22, m2l, m2h);
        float magl = __fsqrt_rn(m2l), magh = __fsqrt_rn(m2h);   // 8*mag, exact
        float uyl, uyh, xsl, xsh;
        upk(uy2, uyl, uyh); upk(xs2, xsl, xsh);
        float oril = atan2f(uyl, xsl);   // == atan2f(gy, xs): scale-invariant
        float orih = atan2f(uyh, xsh);

        u64 ch = f2mul(C36_2, f2add(f2add(pk(oril, orih), TWOPI2), PI2)); // t3

        // ob = rn(t3 / 2pi) via packed Markstein sequence (correctly rounded)
        u64 q0  = f2mul(ch, RCP2);
        u64 rr  = f2fma(NC2PI2, q0, ch);              // exact residual
        u64 ob2 = f2fma(rr, RCP2, q0);

        float obl, obh; upk(ob2, obl, obh);
        // double clamp floor to [36, 71] (see header comment)
        float fbl = fminf(fmaxf(floorf(obl), 36.0f), 71.0f);
        float fbh = fminf(fmaxf(floorf(obh), 36.0f), 71.0f);
        u64 w1f2 = f2fma(pk(fbl, fbh), NONE2, ob2);   // rn(ob - fb), exact fold
        u64 mag2 = pk(magl, magh);
        u64 onem = f2fma(w1f2, NONE2, ONE2);          // rn(1 - w1f)
        u64 w0v2 = f2mul(onem, mag2);
        u64 w1v2 = f2mul(w1f2, mag2);

        float w0l, w0h, w1vl, w1vh;
        upk(w0v2, w0l, w0h); upk(w1v2, w1vl, w1vh);

        // row = floor - 36 in [0, 35]; row+1 in [1, 36]; row 36 = bin-0 alias
        int rl = (int)fbl * 32 - 36 * 32;
        hl[rl]      += w0l;
        hl[rl + 32] += w1vl;
        int rh = (int)fbh * 32 - 36 * 32;
        hl[rh]      += w0h;
        hl[rh + 32] += w1vh;
    };

    // Depth-2 rotation: n1=row(2k+1), n2=row(2k+2), n3=row(2k+3), n4=row(2k+4)
    float r0v = __ldcs(p);            // row 0
    float rm1 = r0v;                  // edge pad: row -1 == row 0
    float n1  = __ldcs(p + 1 * 32);
    float n2  = __ldcs(p + 2 * 32);
    float n3  = __ldcs(p + 3 * 32);
    float n4  = __ldcs(p + 4 * 32);

    #pragma unroll 5
    for (int k = 0; k < 13; ++k) {    // branch-free: loads always in range
        float r1v = n1, r2v = n2;
        n1 = n3; n2 = n4;
        n3 = __ldcs(p + (2 * k + 5) * 32);
        n4 = __ldcs(p + (2 * k + 6) * 32);
        pair_body(rm1, r0v, r1v, r2v);
        rm1 = r1v; r0v = r2v;
    }
    {   // k=13: centers 26,27; only row 31 left to load
        float r1v = n1, r2v = n2;
        n1 = n3; n2 = n4;
        n3 = __ldcs(p + 31 * 32);
        pair_body(rm1, r0v, r1v, r2v);
        rm1 = r1v; r0v = r2v;
    }
    {   // k=14: centers 28,29; no loads
        float r1v = n1, r2v = n2;
        pair_body(rm1, r0v, r1v, r2v);
        rm1 = r1v; r0v = r2v;
    }
    pair_body(rm1, r0v, n3, n3);      // centers 30,31: row 32 clamps to row 31
    __syncwarp();

    // Reduce 32 lane-private copies per row; rotated reads (conflict-free),
    // 2 independent accumulators halve the serial FADD chain (ordering-noise
    // class, tolerated).
    const int rowA = lane;                                  // rows 0..31 (bins 0..31)
    const int rowB = 32 + lane;                             // rows 32..36 (lanes 0..4)
    float sA0 = 0.0f, sA1 = 0.0f, sB0 = 0.0f, sB1 = 0.0f;
    #pragma unroll
    for (int k = 0; k < 32; k += 2) {
        int l0 = (lane + k) & 31;
        int l1 = (lane + k + 1) & 31;
        sA0 = __fadd_rn(sA0, hw[rowA * 32 + l0]);
        sA1 = __fadd_rn(sA1, hw[rowA * 32 + l1]);
        if (lane < 5) {
            sB0 = __fadd_rn(sB0, hw[rowB * 32 + l0]);
            sB1 = __fadd_rn(sB1, hw[rowB * 32 + l1]);
        }
    }
    float s0 = __fadd_rn(sA0, sA1);
    float s1 = __fadd_rn(sB0, sB1);
    __syncwarp();
    // Diagonal slots: slot i at hw[i*32 + (i & 31)]  (bank = i mod 32)
    hw[rowA * 32 + (rowA & 31)] = s0;                       // slots 0..31
    if (lane < 5) hw[rowB * 32 + (rowB & 31)] = s1;         // slots 32..36
    __syncwarp();
    // Fold alias: bin 0 += row 36 (appended-last add order; tolerated class)
    if (lane == 0) hw[0] = __fadd_rn(hw[0], hw[36 * 32 + 4]);
    __syncwarp();

    auto hbin = [&](int b) { return hw[b * 32 + (b & 31)]; };

    // sm[b] = (0.33*h[b-1] + 0.34*h[b]) + 0.33*h[b+1]  (no fma contraction)
    int bm = (lane == 0) ? 35 : lane - 1;
    int bp = lane + 1;   // lane 31 -> bin 32, valid
    float sm0 = __fadd_rn(__fadd_rn(__fmul_rn(0.33f, hbin(bm)),
                                    __fmul_rn(0.34f, hbin(lane))),
                          __fmul_rn(0.33f, hbin(bp)));
    float bv = sm0; int bi = lane;
    if (lane < 4) {
        int bb  = 32 + lane;
        int bm2 = bb - 1;
        int bp2 = (bb == 35) ? 0 : bb + 1;
        float sm1 = __fadd_rn(__fadd_rn(__fmul_rn(0.33f, hbin(bm2)),
                                        __fmul_rn(0.34f, hbin(bb))),
                              __fmul_rn(0.33f, hbin(bp2)));
        if (sm1 > bv) { bv = sm1; bi = bb; }  // strict >: tie keeps lower index
    }
    #pragma unroll
    for (int o = 16; o > 0; o >>= 1) {
        float ov = __shfl_xor_sync(FULLMASK, bv, o);
        int   oi = __shfl_xor_sync(FULLMASK, bi, o);
        if (ov > bv || (ov == bv && oi < bi)) { bv = ov; bi = oi; }
    }
    if (lane == 0) {
        float fi = (float)bi;
        float v  = __fmul_rn(6.28318530717958647692f, fi);
        v = __fdiv_rn(v, 36.0f);
        out[pIdx] = -(__fadd_rn(v, -3.14159265358979323846f));
    }
}

extern "C" void kernel_launch(void* const* d_in, const int* in_sizes, int n_in,
                              void* d_out, int out_size)
{
    cudaFuncSetAttribute(pdgo_kernel,
                         cudaFuncAttributePreferredSharedMemoryCarveout, 100);
    const float* patch = (const float*)d_in[0];
    float* out = (float*)d_out;
    int B = in_sizes[0] / 1024;      // 32*32 per patch
    int blocks = (B + 1) / 2;        // 2 warps (patches) per 64-thread block
    pdgo_kernel<<<blocks, 64>>>(patch, out, B);
}